// round 1
// baseline (speedup 1.0000x reference)
#include <cuda_runtime.h>
#include <stdint.h>

#define N_NODES 100000
#define FEAT    16

// Scratch: device globals (no allocation allowed).
__device__ int    g_deg[N_NODES];        // degree histogram
__device__ int    g_is64;                // 1 if edge_index is int64, 0 if int32
__device__ float4 g_y[N_NODES * 4];      // y[n] = (deg[n]-1)*x[n] + extra[n], 16 floats = 4 float4 per node

// ---------------------------------------------------------------------------
// Kernel 1: zero the degree array.
__global__ void zero_deg_k(int n) {
    int i = blockIdx.x * blockDim.x + threadIdx.x;
    if (i < n) g_deg[i] = 0;
}

// ---------------------------------------------------------------------------
// Kernel 2: detect index dtype. View buffer as int32 words. If dtype is int64
// (values in [0, 1e5), little-endian), words at odd positions are all zero.
// For int32 random values, 1024 consecutive odd words all zero is impossible.
__global__ void detect_k(const int* __restrict__ idx32) {
    __shared__ int nz;
    if (threadIdx.x == 0) nz = 0;
    __syncthreads();
    for (int i = threadIdx.x; i < 1024; i += blockDim.x) {
        if (idx32[2 * i + 1] != 0) nz = 1;   // benign race: only writes 1
    }
    __syncthreads();
    if (threadIdx.x == 0) g_is64 = (nz == 0) ? 1 : 0;
}

// ---------------------------------------------------------------------------
// Kernel 3: degree histogram over src = edge_index[0].
__global__ void count_k(const int* __restrict__ idx32, int nEdges) {
    int e = blockIdx.x * blockDim.x + threadIdx.x;
    int stride = g_is64 ? 2 : 1;
    if (e < nEdges) {
        int s = idx32[(size_t)e * stride];
        atomicAdd(&g_deg[s], 1);
    }
}

// ---------------------------------------------------------------------------
// Kernel 4: y[n] = (deg[n]-1) * x[n] + extra[n], one float4 per thread.
__global__ void node_k(const float4* __restrict__ x,
                       const float4* __restrict__ extra, int n4) {
    int i = blockIdx.x * blockDim.x + threadIdx.x;
    if (i < n4) {
        int n = i >> 2;
        float sc = (float)(g_deg[n] - 1);
        float4 a = x[i];
        float4 b = extra[i];
        float4 r;
        r.x = fmaf(sc, a.x, b.x);
        r.y = fmaf(sc, a.y, b.y);
        r.z = fmaf(sc, a.z, b.z);
        r.w = fmaf(sc, a.w, b.w);
        g_y[i] = r;
    }
}

// ---------------------------------------------------------------------------
// Kernel 5: gather — out[e] = y[src[e]]. 4 threads per edge, one float4 each.
// A warp covers 8 consecutive edges => 512B fully-coalesced stores.
__global__ void gather_k(const int* __restrict__ idx32,
                         float4* __restrict__ out, int nItems) {
    int i = blockIdx.x * blockDim.x + threadIdx.x;
    int stride = g_is64 ? 2 : 1;
    if (i < nItems) {
        int e = i >> 2;
        int c = i & 3;
        int s = __ldg(&idx32[(size_t)e * stride]);   // broadcast hit among 4 lanes
        out[i] = g_y[s * 4 + c];
    }
}

// ---------------------------------------------------------------------------
extern "C" void kernel_launch(void* const* d_in, const int* in_sizes, int n_in,
                              void* d_out, int out_size) {
    const float4* x     = (const float4*)d_in[0];   // [N, 16] fp32
    const float4* extra = (const float4*)d_in[1];   // [N, 16] fp32
    const int*    idx32 = (const int*)d_in[2];      // [2, E] int32 or int64 (int32 view)

    int nNodes = in_sizes[0] / FEAT;                // 100000
    int nEdges = in_sizes[2] / 2;                   // 3.2M (element count of [2,E])
    int n4     = nNodes * 4;
    int nItems = nEdges * 4;

    float4* out = (float4*)d_out;

    zero_deg_k<<<(nNodes + 255) / 256, 256>>>(nNodes);
    detect_k<<<1, 256>>>(idx32);
    count_k<<<(nEdges + 255) / 256, 256>>>(idx32, nEdges);
    node_k<<<(n4 + 255) / 256, 256>>>(x, extra, n4);
    gather_k<<<(nItems + 255) / 256, 256>>>(idx32, out, nItems);
}

// round 2
// speedup vs baseline: 1.1764x; 1.1764x over previous
#include <cuda_runtime.h>
#include <stdint.h>

#define N_NODES 100000
#define FEAT    16

// Scratch: device globals (no allocation allowed).
__device__ int    g_deg[N_NODES];        // degree histogram
__device__ int    g_is64;                // 1 if edge_index is int64, 0 if int32
__device__ float4 g_y[N_NODES * 4];      // y[n] = (deg[n]-1)*x[n] + extra[n]

// ---------------------------------------------------------------------------
// Kernel 1: zero degree array; block 0 additionally detects index dtype.
// int64 values < 2^31 little-endian => all odd int32 words are 0.
__global__ void zero_detect_k(const int* __restrict__ idx32, int n) {
    int i = blockIdx.x * blockDim.x + threadIdx.x;
    if (i < n) g_deg[i] = 0;
    if (blockIdx.x == 0) {
        __shared__ int nz;
        if (threadIdx.x == 0) nz = 0;
        __syncthreads();
        for (int k = threadIdx.x; k < 1024; k += blockDim.x) {
            if (idx32[2 * k + 1] != 0) nz = 1;   // benign race: only writes 1
        }
        __syncthreads();
        if (threadIdx.x == 0) g_is64 = (nz == 0) ? 1 : 0;
    }
}

// ---------------------------------------------------------------------------
// Kernel 2: degree histogram. 2 edges per thread, vectorized index loads.
__global__ void count_k(const int* __restrict__ idx32, int nEdges) {
    int t = blockIdx.x * blockDim.x + threadIdx.x;
    int e0 = t * 2;
    if (e0 >= nEdges) return;
    int s0, s1;
    if (g_is64) {
        // two int64 values = 16B aligned load
        const longlong2* p = (const longlong2*)idx32;
        longlong2 v = __ldcs(&p[t]);
        s0 = (int)v.x; s1 = (int)v.y;
    } else {
        const int2* p = (const int2*)idx32;
        int2 v = __ldcs(&p[t]);
        s0 = v.x; s1 = v.y;
    }
    atomicAdd(&g_deg[s0], 1);
    if (e0 + 1 < nEdges) atomicAdd(&g_deg[s1], 1);
}

// ---------------------------------------------------------------------------
// Kernel 3: y[n] = (deg[n]-1) * x[n] + extra[n], one float4 per thread.
__global__ void node_k(const float4* __restrict__ x,
                       const float4* __restrict__ extra, int n4) {
    int i = blockIdx.x * blockDim.x + threadIdx.x;
    if (i < n4) {
        int n = i >> 2;
        float sc = (float)(g_deg[n] - 1);
        float4 a = x[i];
        float4 b = extra[i];
        float4 r;
        r.x = fmaf(sc, a.x, b.x);
        r.y = fmaf(sc, a.y, b.y);
        r.z = fmaf(sc, a.z, b.z);
        r.w = fmaf(sc, a.w, b.w);
        g_y[i] = r;
    }
}

// ---------------------------------------------------------------------------
// Kernel 4: gather — out[e] = y[src[e]]. 4 lanes per edge (coalesced 512B
// stores per warp). Each thread processes 2 items one block-stride apart:
// two independent load chains (MLP=2) while staying fully coalesced.
__global__ void gather_k(const int* __restrict__ idx32,
                         float4* __restrict__ out, int nItems) {
    int tile = blockIdx.x * (blockDim.x * 2);
    int i0 = tile + threadIdx.x;
    int i1 = i0 + blockDim.x;
    int stride = g_is64 ? 2 : 1;

    if (i0 < nItems) {
        int e0 = i0 >> 2, c0 = i0 & 3;
        int s0 = __ldcs(&idx32[(size_t)e0 * stride]);
        // issue second chain before consuming first
        if (i1 < nItems) {
            int e1 = i1 >> 2, c1 = i1 & 3;
            int s1 = __ldcs(&idx32[(size_t)e1 * stride]);
            float4 v0 = g_y[s0 * 4 + c0];
            float4 v1 = g_y[s1 * 4 + c1];
            __stcs(&out[i0], v0);
            __stcs(&out[i1], v1);
        } else {
            float4 v0 = g_y[s0 * 4 + c0];
            __stcs(&out[i0], v0);
        }
    }
}

// ---------------------------------------------------------------------------
extern "C" void kernel_launch(void* const* d_in, const int* in_sizes, int n_in,
                              void* d_out, int out_size) {
    const float4* x     = (const float4*)d_in[0];   // [N, 16] fp32
    const float4* extra = (const float4*)d_in[1];   // [N, 16] fp32
    const int*    idx32 = (const int*)d_in[2];      // [2, E] int64/int32 (int32 view)

    int nNodes = in_sizes[0] / FEAT;                // 100000
    int nEdges = in_sizes[2] / 2;                   // 3.2M
    int n4     = nNodes * 4;
    int nItems = nEdges * 4;                        // 12.8M float4 items

    float4* out = (float4*)d_out;

    zero_detect_k<<<(nNodes + 255) / 256, 256>>>(idx32, nNodes);

    int cThreads = (nEdges + 1) / 2;
    count_k<<<(cThreads + 255) / 256, 256>>>(idx32, nEdges);

    node_k<<<(n4 + 255) / 256, 256>>>(x, extra, n4);

    int gBlocks = (nItems + 511) / 512;             // 256 threads x 2 items
    gather_k<<<gBlocks, 256>>>(idx32, out, nItems);
}

// round 3
// speedup vs baseline: 1.2400x; 1.0541x over previous
#include <cuda_runtime.h>
#include <stdint.h>

#define N_NODES 100000
#define FEAT    16

// Scratch: device globals (no allocation allowed).
__device__ int    g_deg[N_NODES];        // degree histogram
__device__ int    g_is64;                // 1 if edge_index is int64, 0 if int32
__device__ float4 g_y[N_NODES * 4];      // y[n] = (deg[n]-1)*x[n] + extra[n]

// ---------------------------------------------------------------------------
// Kernel 1: zero degree array; block 0 additionally detects index dtype.
// int64 values < 2^31 little-endian => all odd int32 words are 0.
__global__ void zero_detect_k(const int* __restrict__ idx32, int n) {
    int i = blockIdx.x * blockDim.x + threadIdx.x;
    if (i < n) g_deg[i] = 0;
    if (blockIdx.x == 0) {
        __shared__ int nz;
        if (threadIdx.x == 0) nz = 0;
        __syncthreads();
        for (int k = threadIdx.x; k < 1024; k += blockDim.x) {
            if (idx32[2 * k + 1] != 0) nz = 1;   // benign race: only writes 1
        }
        __syncthreads();
        if (threadIdx.x == 0) g_is64 = (nz == 0) ? 1 : 0;
    }
}

// ---------------------------------------------------------------------------
// Kernel 2: degree histogram. 4 edges per thread, 16B vector index loads.
__global__ void count_k(const int* __restrict__ idx32, int nEdges) {
    int t = blockIdx.x * blockDim.x + threadIdx.x;
    int e0 = t * 4;
    if (e0 >= nEdges) return;
    int s0, s1, s2, s3;
    if (g_is64) {
        const longlong2* p = (const longlong2*)idx32;   // 2 int64 per 16B
        longlong2 v0 = __ldcs(&p[t * 2]);
        longlong2 v1 = __ldcs(&p[t * 2 + 1]);
        s0 = (int)v0.x; s1 = (int)v0.y; s2 = (int)v1.x; s3 = (int)v1.y;
    } else {
        const int4* p = (const int4*)idx32;             // 4 int32 per 16B
        int4 v = __ldcs(&p[t]);
        s0 = v.x; s1 = v.y; s2 = v.z; s3 = v.w;
    }
    // nEdges = 3.2M divisible by 4, but guard the tail anyway
    atomicAdd(&g_deg[s0], 1);
    if (e0 + 1 < nEdges) atomicAdd(&g_deg[s1], 1);
    if (e0 + 2 < nEdges) atomicAdd(&g_deg[s2], 1);
    if (e0 + 3 < nEdges) atomicAdd(&g_deg[s3], 1);
}

// ---------------------------------------------------------------------------
// Kernel 3: y[n] = (deg[n]-1) * x[n] + extra[n], one float4 per thread.
__global__ void node_k(const float4* __restrict__ x,
                       const float4* __restrict__ extra, int n4) {
    int i = blockIdx.x * blockDim.x + threadIdx.x;
    if (i < n4) {
        int n = i >> 2;
        float sc = (float)(g_deg[n] - 1);
        float4 a = x[i];
        float4 b = extra[i];
        float4 r;
        r.x = fmaf(sc, a.x, b.x);
        r.y = fmaf(sc, a.y, b.y);
        r.z = fmaf(sc, a.z, b.z);
        r.w = fmaf(sc, a.w, b.w);
        g_y[i] = r;
    }
}

// ---------------------------------------------------------------------------
// Kernel 4: gather — out[e] = y[src[e]]. 4 lanes per edge (64B-dense y lines,
// 128B-coalesced stores). 4 items per thread, one block-stride apart:
// 4 independent idx->y chains in flight (MLP=4).
__global__ void gather_k(const int* __restrict__ idx32,
                         float4* __restrict__ out, int nItems) {
    int bd   = blockDim.x;
    int tile = blockIdx.x * (bd * 4);
    int i0 = tile + threadIdx.x;
    int i1 = i0 + bd;
    int i2 = i1 + bd;
    int i3 = i2 + bd;
    int stride = g_is64 ? 2 : 1;

    // Fast path: full tile (all but the last block)
    if (i3 < nItems) {
        int s0 = __ldcs(&idx32[(size_t)(i0 >> 2) * stride]);
        int s1 = __ldcs(&idx32[(size_t)(i1 >> 2) * stride]);
        int s2 = __ldcs(&idx32[(size_t)(i2 >> 2) * stride]);
        int s3 = __ldcs(&idx32[(size_t)(i3 >> 2) * stride]);
        float4 v0 = g_y[s0 * 4 + (i0 & 3)];
        float4 v1 = g_y[s1 * 4 + (i1 & 3)];
        float4 v2 = g_y[s2 * 4 + (i2 & 3)];
        float4 v3 = g_y[s3 * 4 + (i3 & 3)];
        __stcs(&out[i0], v0);
        __stcs(&out[i1], v1);
        __stcs(&out[i2], v2);
        __stcs(&out[i3], v3);
    } else {
        #pragma unroll
        for (int k = 0; k < 4; k++) {
            int i = tile + threadIdx.x + k * bd;
            if (i < nItems) {
                int s = __ldcs(&idx32[(size_t)(i >> 2) * stride]);
                float4 v = g_y[s * 4 + (i & 3)];
                __stcs(&out[i], v);
            }
        }
    }
}

// ---------------------------------------------------------------------------
extern "C" void kernel_launch(void* const* d_in, const int* in_sizes, int n_in,
                              void* d_out, int out_size) {
    const float4* x     = (const float4*)d_in[0];   // [N, 16] fp32
    const float4* extra = (const float4*)d_in[1];   // [N, 16] fp32
    const int*    idx32 = (const int*)d_in[2];      // [2, E] int64/int32 (int32 view)

    int nNodes = in_sizes[0] / FEAT;                // 100000
    int nEdges = in_sizes[2] / 2;                   // 3.2M
    int n4     = nNodes * 4;
    int nItems = nEdges * 4;                        // 12.8M float4 items

    float4* out = (float4*)d_out;

    zero_detect_k<<<(nNodes + 255) / 256, 256>>>(idx32, nNodes);

    int cThreads = (nEdges + 3) / 4;
    count_k<<<(cThreads + 255) / 256, 256>>>(idx32, nEdges);

    node_k<<<(n4 + 255) / 256, 256>>>(x, extra, n4);

    int gBlocks = (nItems + 1023) / 1024;           // 256 threads x 4 items
    gather_k<<<gBlocks, 256>>>(idx32, out, nItems);
}